// round 1
// baseline (speedup 1.0000x reference)
#include <cuda_runtime.h>

// Problem constants
#define POOL 7
#define NUM_ROIS 256
#define H_IMG 128
#define W_IMG 128
#define C_IMG 1024
#define SCALE (1.0f / 16.0f)

// One CTA per (roi, cell). 256 threads; each thread handles one float4
// (4 channels): 256 * 4 = 1024 channels.
// Output layout: (1, 256, 7, 7, 1024) row-major.
// Img layout:    (1, 128, 128, 1024) row-major.
__global__ void __launch_bounds__(256, 8)
roi_pool_kernel(const float* __restrict__ img,
                const float* __restrict__ rois,
                float* __restrict__ out)
{
    const int cell = blockIdx.x;   // 0..48
    const int roi  = blockIdx.y;   // 0..255
    const int iy   = cell / POOL;
    const int ix   = cell % POOL;

    // Scalar ROI math (cheap, recomputed per thread; rois is tiny & L1-broadcast)
    const float4 r = *(const float4*)(rois + roi * 4);
    const int x0 = (int)(r.x * SCALE);
    const int y0 = (int)(r.y * SCALE);
    const int w  = (int)(r.z * SCALE);
    const int h  = (int)(r.w * SCALE);

    // Match reference arithmetic order: step = float(h)/POOL, s = i*step
    const float sy = (float)iy * ((float)h / (float)POOL);
    const float sx = (float)ix * ((float)w / (float)POOL);
    const float fy = floorf(sy);
    const float fx = floorf(sx);
    const float ty = sy - fy;
    const float tx = sx - fx;
    const int y_lo = (int)fy;
    const int x_lo = (int)fx;
    const int y_hi = min(y_lo + 1, max(h - 1, 0));
    const int x_hi = min(x_lo + 1, max(w - 1, 0));
    const int gy0 = min(max(y0 + y_lo, 0), H_IMG - 1);
    const int gy1 = min(max(y0 + y_hi, 0), H_IMG - 1);
    const int gx0 = min(max(x0 + x_lo, 0), W_IMG - 1);
    const int gx1 = min(max(x0 + x_hi, 0), W_IMG - 1);

    // Corner row pointers (each row-pixel is 1024 floats = 256 float4)
    const float4* p00 = (const float4*)(img + ((size_t)(gy0 * W_IMG + gx0) << 10));
    const float4* p01 = (const float4*)(img + ((size_t)(gy0 * W_IMG + gx1) << 10));
    const float4* p10 = (const float4*)(img + ((size_t)(gy1 * W_IMG + gx0) << 10));
    const float4* p11 = (const float4*)(img + ((size_t)(gy1 * W_IMG + gx1) << 10));

    const int c = threadIdx.x;  // float4 index 0..255

    const float4 v00 = p00[c];
    const float4 v01 = p01[c];
    const float4 v10 = p10[c];
    const float4 v11 = p11[c];

    float4 o;
    {
        float top = v00.x + tx * (v01.x - v00.x);
        float bot = v10.x + tx * (v11.x - v10.x);
        o.x = top + ty * (bot - top);
    }
    {
        float top = v00.y + tx * (v01.y - v00.y);
        float bot = v10.y + tx * (v11.y - v10.y);
        o.y = top + ty * (bot - top);
    }
    {
        float top = v00.z + tx * (v01.z - v00.z);
        float bot = v10.z + tx * (v11.z - v10.z);
        o.z = top + ty * (bot - top);
    }
    {
        float top = v00.w + tx * (v01.w - v00.w);
        float bot = v10.w + tx * (v11.w - v10.w);
        o.w = top + ty * (bot - top);
    }

    float4* out4 = (float4*)out;
    out4[((size_t)(roi * (POOL * POOL) + cell) << 8) + c] = o;
}

extern "C" void kernel_launch(void* const* d_in, const int* in_sizes, int n_in,
                              void* d_out, int out_size)
{
    const float* img  = (const float*)d_in[0];
    const float* rois = (const float*)d_in[1];
    float* out = (float*)d_out;

    dim3 grid(POOL * POOL, NUM_ROIS);
    roi_pool_kernel<<<grid, 256>>>(img, rois, out);
}

// round 2
// speedup vs baseline: 1.0828x; 1.0828x over previous
#include <cuda_runtime.h>

// Problem constants
#define POOL 7
#define NUM_ROIS 256
#define H_IMG 128
#define W_IMG 128
#define C_IMG 1024
#define SCALE (1.0f / 16.0f)

// One CTA per (roi, cell). 128 threads; each thread handles TWO float4
// chunks (c and c+128) => 8 independent LDG.128 in flight per thread.
// Output layout: (1, 256, 7, 7, 1024) row-major.
// Img layout:    (1, 128, 128, 1024) row-major.
__global__ void __launch_bounds__(128, 10)
roi_pool_kernel(const float* __restrict__ img,
                const float* __restrict__ rois,
                float* __restrict__ out)
{
    const int cell = blockIdx.x;   // 0..48
    const int roi  = blockIdx.y;   // 0..255
    const int iy   = cell / POOL;
    const int ix   = cell % POOL;

    // Scalar ROI math (cheap; rois tiny & L1-broadcast)
    const float4 r = *(const float4*)(rois + roi * 4);
    const int x0 = (int)(r.x * SCALE);
    const int y0 = (int)(r.y * SCALE);
    const int w  = (int)(r.z * SCALE);
    const int h  = (int)(r.w * SCALE);

    // Match reference arithmetic order exactly
    const float sy = (float)iy * ((float)h / (float)POOL);
    const float sx = (float)ix * ((float)w / (float)POOL);
    const float fy = floorf(sy);
    const float fx = floorf(sx);
    const float ty = sy - fy;
    const float tx = sx - fx;
    const int y_lo = (int)fy;
    const int x_lo = (int)fx;
    const int y_hi = min(y_lo + 1, max(h - 1, 0));
    const int x_hi = min(x_lo + 1, max(w - 1, 0));
    const int gy0 = min(max(y0 + y_lo, 0), H_IMG - 1);
    const int gy1 = min(max(y0 + y_hi, 0), H_IMG - 1);
    const int gx0 = min(max(x0 + x_lo, 0), W_IMG - 1);
    const int gx1 = min(max(x0 + x_hi, 0), W_IMG - 1);

    const float4* p00 = (const float4*)(img + ((size_t)(gy0 * W_IMG + gx0) << 10));
    const float4* p01 = (const float4*)(img + ((size_t)(gy0 * W_IMG + gx1) << 10));
    const float4* p10 = (const float4*)(img + ((size_t)(gy1 * W_IMG + gx0) << 10));
    const float4* p11 = (const float4*)(img + ((size_t)(gy1 * W_IMG + gx1) << 10));

    const int c = threadIdx.x;        // 0..127

    // Batch all 8 loads up front -> MLP=8 per thread
    const float4 a00 = p00[c];
    const float4 a01 = p01[c];
    const float4 a10 = p10[c];
    const float4 a11 = p11[c];
    const float4 b00 = p00[c + 128];
    const float4 b01 = p01[c + 128];
    const float4 b10 = p10[c + 128];
    const float4 b11 = p11[c + 128];

    float4 oa, ob;
    #define LERP2(O, V00, V01, V10, V11, F)                         \
        {                                                           \
            float top = V00.F + tx * (V01.F - V00.F);               \
            float bot = V10.F + tx * (V11.F - V10.F);               \
            O.F = top + ty * (bot - top);                           \
        }
    LERP2(oa, a00, a01, a10, a11, x)
    LERP2(oa, a00, a01, a10, a11, y)
    LERP2(oa, a00, a01, a10, a11, z)
    LERP2(oa, a00, a01, a10, a11, w)
    LERP2(ob, b00, b01, b10, b11, x)
    LERP2(ob, b00, b01, b10, b11, y)
    LERP2(ob, b00, b01, b10, b11, z)
    LERP2(ob, b00, b01, b10, b11, w)
    #undef LERP2

    float4* out4 = (float4*)out;
    const size_t base = ((size_t)(roi * (POOL * POOL) + cell)) << 8;
    out4[base + c]       = oa;
    out4[base + c + 128] = ob;
}

extern "C" void kernel_launch(void* const* d_in, const int* in_sizes, int n_in,
                              void* d_out, int out_size)
{
    const float* img  = (const float*)d_in[0];
    const float* rois = (const float*)d_in[1];
    float* out = (float*)d_out;

    dim3 grid(POOL * POOL, NUM_ROIS);
    roi_pool_kernel<<<grid, 128>>>(img, rois, out);
}